// round 4
// baseline (speedup 1.0000x reference)
#include <cuda_runtime.h>

// Problem constants (fixed by the reference hparams)
#define BB    32          // batch
#define NSEG  108         // MAX_NUM_SEG
#define NTOT  3456        // BB*NSEG
#define SS    64          // candidates per segment
#define TX    2560        // MAX_LEN_PAD
#define DD    80          // feature dim
#define D4    20          // DD / 4 (float4 units)
#define MINSEG 19

// Scratch (no allocations allowed -> __device__ globals)
__device__ int g_offset[NTOT];      // exclusive per-batch cumsum of len_seg
__device__ int g_cnt[NTOT];         // masked-candidate count per segment
__device__ int g_segbase[NTOT + 1]; // exclusive scan of g_cnt, [NTOT] = total
__device__ int g_rows;              // total / BB

// ---------------------------------------------------------------------------
// Kernel 1: per-batch segment offsets + per-segment counts.
// Count = #{ s in [0,64) : floorf(s/scale) < L }, monotone in s -> binary search
// with true IEEE division (__fdiv_rn) so boundaries match the reference exactly.
// ---------------------------------------------------------------------------
__global__ void k_prep(const int* __restrict__ len_seq,
                       const float* __restrict__ scales_u,
                       const int* __restrict__ len_seg_raw) {
    const int b = blockIdx.x;
    __shared__ int sh_len[NSEG];
    __shared__ int sh_off[NSEG];
    const int tid = threadIdx.x;

    if (tid < NSEG) sh_len[tid] = len_seg_raw[b * NSEG + tid] + MINSEG;
    __syncthreads();
    if (tid == 0) {
        int acc = 0;
        for (int k = 0; k < NSEG; k++) { sh_off[k] = acc; acc += sh_len[k]; }
    }
    __syncthreads();

    if (tid < NSEG) {
        const int n   = b * NSEG + tid;
        const int off = sh_off[tid];
        g_offset[n] = off;

        const int L = min(sh_len[tid] - 1, len_seq[b] - 1 - off);
        int cnt = 0;
        if (L > 0) {
            const float scale = scales_u[n] + 0.5f;
            const float Lf = (float)L;
            if (floorf(__fdiv_rn(63.0f, scale)) < Lf) {
                cnt = SS;  // all 64 candidates pass
            } else {
                // invariant: cond(lo)=true (cond(0): 0 < Lf since L>0), cond(hi)=false
                int lo = 0, hi = 63;
                while (hi - lo > 1) {
                    const int mid = (lo + hi) >> 1;
                    if (floorf(__fdiv_rn((float)mid, scale)) < Lf) lo = mid;
                    else hi = mid;
                }
                cnt = lo + 1;
            }
        }
        g_cnt[n] = cnt;
    }
}

// ---------------------------------------------------------------------------
// Kernel 2: exclusive scan of 3456 counts (single block, 1024 threads, 4/thread)
// ---------------------------------------------------------------------------
__global__ void k_scan() {
    __shared__ int part[1024];
    const int tid = threadIdx.x;
    const int base = tid * 4;

    int v0 = 0, v1 = 0, v2 = 0, v3 = 0;
    if (tid < NTOT / 4) {  // 864 active threads
        v0 = g_cnt[base + 0];
        v1 = g_cnt[base + 1];
        v2 = g_cnt[base + 2];
        v3 = g_cnt[base + 3];
    }
    const int s1 = v0 + v1;
    const int s2 = s1 + v2;
    const int s3 = s2 + v3;
    part[tid] = s3;
    __syncthreads();

    // Hillis-Steele inclusive scan over 1024 partials
    for (int off = 1; off < 1024; off <<= 1) {
        int v = (tid >= off) ? part[tid - off] : 0;
        __syncthreads();
        part[tid] += v;
        __syncthreads();
    }

    const int ex = part[tid] - s3;  // exclusive base for this chunk
    if (tid < NTOT / 4) {
        g_segbase[base + 0] = ex;
        g_segbase[base + 1] = ex + v0;
        g_segbase[base + 2] = ex + s1;
        g_segbase[base + 3] = ex + s2;
    }
    if (tid == 1023) {
        const int total = part[1023];
        g_segbase[NTOT] = total;
        g_rows = total / BB;
    }
}

// ---------------------------------------------------------------------------
// Kernel 3: gather. One block = 32 output rows (all in the same output batch:
// 2560 % 32 == 0). Phase 1: 32 threads invert compaction (binary search over
// seg_base) -> per-row (src_row, lambda). Phase 2: 320 threads stream 640
// float4 (32 rows x 20) with exactly 2 iterations, fully coalesced.
// ---------------------------------------------------------------------------
__global__ void __launch_bounds__(320) k_gather(const float* __restrict__ x,
                                                const float* __restrict__ scales_u,
                                                float* __restrict__ out) {
    __shared__ int   sh_src[32];  // src batch*TX + frame index, -1 = write zeros
    __shared__ float sh_lam[32];

    const int tid = threadIdx.x;
    const int rowbase = blockIdx.x * 32;

    if (tid < 32) {
        const int r = rowbase + tid;
        const int b_out = r / TX;
        const int t = r - b_out * TX;
        const int rows = g_rows;

        int srow = -1;
        float lam = 0.0f;
        if (t < rows) {
            const int p = b_out * rows + t;  // p < total always
            // binary search: largest n with seg_base[n] <= p
            int lo = 0, hi = NTOT;
            while (hi - lo > 1) {
                const int mid = (lo + hi) >> 1;
                if (g_segbase[mid] <= p) lo = mid;
                else hi = mid;
            }
            const int n = lo;
            const int s = p - g_segbase[n];

            const float v  = __fdiv_rn((float)s, scales_u[n] + 0.5f);
            const float fl = floorf(v);
            lam = v - fl;
            int i = (int)(fl + (float)g_offset[n]);  // exact small ints in fp32
            if (i > TX - 2) i = TX - 2;
            if (i < 0) i = 0;
            srow = (n / NSEG) * TX + i;
        }
        sh_src[tid] = srow;
        sh_lam[tid] = lam;
    }
    __syncthreads();

    const float4* __restrict__ x4 = (const float4*)x;
    float4* __restrict__ o4 = (float4*)out;
    const long obase = (long)rowbase * D4;

#pragma unroll
    for (int q = tid; q < 32 * D4; q += 320) {
        const int row = q / D4;
        const int d4  = q - row * D4;
        float4 res;
        const int srow = sh_src[row];
        if (srow >= 0) {
            const float lam = sh_lam[row];
            const float om  = 1.0f - lam;
            const long sbase = (long)srow * D4 + d4;
            const float4 a = x4[sbase];
            const float4 c = x4[sbase + D4];
            res.x = om * a.x + lam * c.x;
            res.y = om * a.y + lam * c.y;
            res.z = om * a.z + lam * c.z;
            res.w = om * a.w + lam * c.w;
        } else {
            res.x = res.y = res.z = res.w = 0.0f;
        }
        o4[obase + q] = res;
    }
}

// ---------------------------------------------------------------------------
extern "C" void kernel_launch(void* const* d_in, const int* in_sizes, int n_in,
                              void* d_out, int out_size) {
    const float* x           = (const float*)d_in[0];  // (32, 2560, 80) f32
    const int*   len_seq     = (const int*)d_in[1];    // (32,) i32
    const float* scales_u    = (const float*)d_in[2];  // (3456,) f32
    const int*   len_seg_raw = (const int*)d_in[3];    // (3456,) i32
    float*       out         = (float*)d_out;          // (32, 2560, 80) f32

    k_prep<<<BB, 128>>>(len_seq, scales_u, len_seg_raw);
    k_scan<<<1, 1024>>>();
    k_gather<<<(BB * TX) / 32, 320>>>(x, scales_u, out);
}